// round 3
// baseline (speedup 1.0000x reference)
#include <cuda_runtime.h>
#include <cuda_bf16.h>
#include <math_constants.h>

// Problem constants (fixed shapes)
#define BB 64
#define LL 512
#define HH 768
#define TT 9
#define NROWS (BB * LL)

__device__ float g_llh[BB];
__device__ float g_logits_scratch[BB * LL * TT];   // fallback if out has no room

// ---------------------------------------------------------------------------
// Kernel A: logits = hidden @ W + b
// Warp computes 4 rows. hidden via float4 LDG (double buffered), W in smem
// with bank-swizzled layout idx = 9k + t + (k>>5): for lane-consecutive
// k = 4*lane+kk the bank pattern is (4l + (l>>3)) mod 32 -> all distinct.
// ---------------------------------------------------------------------------
__global__ __launch_bounds__(128) void logits_kernel(
    const float* __restrict__ hidden,
    const float* __restrict__ W,
    const float* __restrict__ bias,
    float* __restrict__ logits)
{
    __shared__ float Ws[HH * TT + (HH >> 5)];   // 6936 floats
    __shared__ float bs[TT];

    for (int i = threadIdx.x; i < HH * TT; i += 128) {
        int k = i / 9;
        int t = i - 9 * k;
        Ws[9 * k + t + (k >> 5)] = W[i];
    }
    if (threadIdx.x < TT) bs[threadIdx.x] = bias[threadIdx.x];
    __syncthreads();

    const int lane   = threadIdx.x & 31;
    const int gwarp  = (blockIdx.x * 128 + threadIdx.x) >> 5;
    const int nwarps = (gridDim.x * 128) >> 5;

    for (int rb = gwarp * 4; rb < NROWS; rb += nwarps * 4) {
        const float4* h0 = (const float4*)(hidden + (size_t)rb * HH);

        float acc[4][TT];
        #pragma unroll
        for (int r = 0; r < 4; r++)
            #pragma unroll
            for (int t = 0; t < TT; t++) acc[r][t] = bs[t] * 0.03125f;

        float4 hbuf[2][4];
        #pragma unroll
        for (int r = 0; r < 4; r++) hbuf[0][r] = h0[r * (HH / 4) + lane];

        #pragma unroll
        for (int it = 0; it < 6; it++) {
            const int cur = it & 1;
            if (it < 5) {
                #pragma unroll
                for (int r = 0; r < 4; r++)
                    hbuf[cur ^ 1][r] = h0[r * (HH / 4) + (it + 1) * 32 + lane];
            }
            const int kbase = it * 128 + lane * 4;
            #pragma unroll
            for (int kk = 0; kk < 4; kk++) {
                const int k = kbase + kk;
                const float* wrow = &Ws[9 * k + (k >> 5)];
                float hv[4];
                hv[0] = (kk == 0) ? hbuf[cur][0].x : (kk == 1) ? hbuf[cur][0].y : (kk == 2) ? hbuf[cur][0].z : hbuf[cur][0].w;
                hv[1] = (kk == 0) ? hbuf[cur][1].x : (kk == 1) ? hbuf[cur][1].y : (kk == 2) ? hbuf[cur][1].z : hbuf[cur][1].w;
                hv[2] = (kk == 0) ? hbuf[cur][2].x : (kk == 1) ? hbuf[cur][2].y : (kk == 2) ? hbuf[cur][2].z : hbuf[cur][2].w;
                hv[3] = (kk == 0) ? hbuf[cur][3].x : (kk == 1) ? hbuf[cur][3].y : (kk == 2) ? hbuf[cur][3].z : hbuf[cur][3].w;
                #pragma unroll
                for (int t = 0; t < TT; t++) {
                    float w = wrow[t];
                    #pragma unroll
                    for (int r = 0; r < 4; r++)
                        acc[r][t] = fmaf(hv[r], w, acc[r][t]);
                }
            }
        }

        // full butterfly reduce (every lane ends with all 36 sums)
        #pragma unroll
        for (int r = 0; r < 4; r++)
            #pragma unroll
            for (int t = 0; t < TT; t++)
                #pragma unroll
                for (int off = 16; off > 0; off >>= 1)
                    acc[r][t] += __shfl_xor_sync(0xffffffffu, acc[r][t], off);

        // coalesced predicated store: word idx written by lane (idx & 31)
        float* o = logits + (size_t)rb * TT;
        #pragma unroll
        for (int r = 0; r < 4; r++)
            #pragma unroll
            for (int t = 0; t < TT; t++) {
                const int idx = r * TT + t;
                if ((idx & 31) == lane) o[idx] = acc[r][t];
            }
    }
}

// ---------------------------------------------------------------------------
// Kernel B: per-batch CRF. Block = 2 warps. Warp 0: linear-domain scan
// (q[j] = exp(score[j] - 2^E scaling), recurrence is a 9x9 matvec with
// precomputed exp(trans) and prefetched exp(emit); power-of-two rescale every
// 8 steps; single log at the end). Warp 1: numerator.
// ---------------------------------------------------------------------------
__global__ __launch_bounds__(64) void crf_kernel(
    const float* __restrict__ logits,
    const int*   __restrict__ mask,
    const int*   __restrict__ labels,
    const float* __restrict__ start_trans,
    const float* __restrict__ end_trans,
    const float* __restrict__ trans)
{
    __shared__ float e_s[LL * TT];
    __shared__ float m_s[LL];
    __shared__ int   lab_s[LL];
    __shared__ float tr_s[TT * TT];
    __shared__ float st_s[TT];
    __shared__ float en_s[TT];
    __shared__ float num_sh;

    const int b    = blockIdx.x;
    const int tid  = threadIdx.x;
    const int lane = tid & 31;
    const int warp = tid >> 5;

    const float* lg = logits + (size_t)b * LL * TT;
    #pragma unroll 8
    for (int i = tid; i < LL * TT; i += 64) e_s[i] = lg[i];
    for (int i = tid; i < LL; i += 64) {
        int l = labels[(size_t)b * LL + i];
        lab_s[i] = (l == -100) ? 0 : l;
        m_s[i]   = (float)mask[(size_t)b * LL + i];
    }
    if (tid < TT * TT) tr_s[tid] = trans[tid];
    if (tid < TT) { st_s[tid] = start_trans[tid]; en_s[tid] = end_trans[tid]; }
    __syncthreads();

    const float L2E = 1.4426950408889634f;
    const float LN2 = 0.6931471805599453f;

    // ---- numerator (warp 1) ----
    if (warp == 1) {
        float acc = 0.f;
        int   msum = 0;
        for (int t = lane; t < LL; t += 32) {
            msum += (m_s[t] != 0.f) ? 1 : 0;
            if (t >= 1) {
                int lp = lab_s[t - 1], lt = lab_s[t];
                acc = fmaf(tr_s[lp * TT + lt] + e_s[t * TT + lt], m_s[t], acc);
            }
        }
        #pragma unroll
        for (int off = 16; off > 0; off >>= 1) {
            acc  += __shfl_xor_sync(0xffffffffu, acc, off);
            msum += __shfl_xor_sync(0xffffffffu, msum, off);
        }
        if (lane == 0) {
            int seq_end = msum - 1;
            if (seq_end < 0) seq_end = 0;
            int l0 = lab_s[0];
            int llast = lab_s[seq_end];
            num_sh = st_s[l0] + e_s[l0] + acc + en_s[llast];
        }
    }

    // ---- denominator scan (warp 0), linear domain ----
    float denom = 0.f;
    if (warp == 0) {
        const int j = (lane < TT) ? lane : (TT - 1);

        // et[k] = exp(trans[k][j])
        float et0 = exp2f(tr_s[0 * TT + j] * L2E);
        float et1 = exp2f(tr_s[1 * TT + j] * L2E);
        float et2 = exp2f(tr_s[2 * TT + j] * L2E);
        float et3 = exp2f(tr_s[3 * TT + j] * L2E);
        float et4 = exp2f(tr_s[4 * TT + j] * L2E);
        float et5 = exp2f(tr_s[5 * TT + j] * L2E);
        float et6 = exp2f(tr_s[6 * TT + j] * L2E);
        float et7 = exp2f(tr_s[7 * TT + j] * L2E);
        float et8 = exp2f(tr_s[8 * TT + j] * L2E);

        // q = exp(start[j] + e0[j]); E tracks the power-of-two scale
        float q = exp2f((st_s[j] + e_s[j]) * L2E);
        int   E = 0;

        float eej_next = exp2f(e_s[1 * TT + j] * L2E);
        float ms_next  = m_s[1];

        for (int t = 1; t < LL; t++) {
            const float eej = eej_next;
            const float ms  = ms_next;
            if (t < LL - 1) {
                eej_next = exp2f(e_s[(t + 1) * TT + j] * L2E);
                ms_next  = m_s[t + 1];
            }

            float p0 = __shfl_sync(0xffffffffu, q, 0);
            float p1 = __shfl_sync(0xffffffffu, q, 1);
            float p2 = __shfl_sync(0xffffffffu, q, 2);
            float p3 = __shfl_sync(0xffffffffu, q, 3);
            float p4 = __shfl_sync(0xffffffffu, q, 4);
            float p5 = __shfl_sync(0xffffffffu, q, 5);
            float p6 = __shfl_sync(0xffffffffu, q, 6);
            float p7 = __shfl_sync(0xffffffffu, q, 7);
            float p8 = __shfl_sync(0xffffffffu, q, 8);

            float a = fmaf(p1, et1, p0 * et0);  a = fmaf(p2, et2, a);
            float bb2 = fmaf(p4, et4, p3 * et3); bb2 = fmaf(p5, et5, bb2);
            float c = fmaf(p7, et7, p6 * et6);  c = fmaf(p8, et8, c);
            float s = ((a + bb2) + c) * eej;

            q = (ms != 0.f) ? s : q;

            if ((t & 7) == 7) {
                float q0 = __shfl_sync(0xffffffffu, q, 0);
                int ex = (__float_as_int(q0) >> 23) & 0xFF;
                float sc = __int_as_float((254 - ex) << 23);  // 2^(127-ex)
                q *= sc;
                E += ex - 127;
            }
        }

        // denom = ln( sum_j q[j]*exp(end[j]) ) + E*ln2
        float v = (lane < TT) ? q * exp2f(en_s[j] * L2E) : 0.f;
        #pragma unroll
        for (int off = 16; off > 0; off >>= 1)
            v += __shfl_xor_sync(0xffffffffu, v, off);
        denom = LN2 * (__log2f(v) + (float)E);
    }

    __syncthreads();   // num_sh ready
    if (warp == 0 && lane == 0)
        g_llh[b] = num_sh - denom;
}

// ---------------------------------------------------------------------------
// Kernel C: loss = -mean(llh), deterministic tree reduce
// ---------------------------------------------------------------------------
__global__ void loss_kernel(float* __restrict__ loss_out)
{
    int lane = threadIdx.x;   // 32 threads
    float v = g_llh[lane] + g_llh[lane + 32];
    #pragma unroll
    for (int off = 16; off > 0; off >>= 1)
        v += __shfl_xor_sync(0xffffffffu, v, off);
    if (lane == 0) loss_out[0] = -v * (1.0f / (float)BB);
}

// ---------------------------------------------------------------------------
extern "C" void kernel_launch(void* const* d_in, const int* in_sizes, int n_in,
                              void* d_out, int out_size)
{
    const float* hidden      = (const float*)d_in[0];
    const int*   attn_mask   = (const int*)d_in[1];
    const int*   labels      = (const int*)d_in[2];   // int32 (JAX x64 disabled)
    const float* W           = (const float*)d_in[3];
    const float* bias        = (const float*)d_in[4];
    const float* start_trans = (const float*)d_in[5];
    const float* end_trans   = (const float*)d_in[6];
    const float* trans       = (const float*)d_in[7];

    float* out = (float*)d_out;

    static float* scratch = nullptr;
    if (!scratch) {
        void* p = nullptr;
        cudaGetSymbolAddress(&p, g_logits_scratch);
        scratch = (float*)p;
    }

    const int NLOG = BB * LL * TT;   // 294912
    float* loss_ptr;
    float* logits_ptr;
    if (out_size >= NLOG + 1) {          // (loss, logits) concatenated
        loss_ptr   = out;
        logits_ptr = out + 1;
    } else if (out_size == NLOG) {       // logits only
        loss_ptr   = scratch;
        logits_ptr = out;
    } else {                             // loss only
        loss_ptr   = out;
        logits_ptr = scratch;
    }

    logits_kernel<<<2048, 128>>>(hidden, W, bias, logits_ptr);
    crf_kernel<<<BB, 64>>>(logits_ptr, attn_mask, labels,
                           start_trans, end_trans, trans);
    loss_kernel<<<1, 32>>>(loss_ptr);
}

// round 4
// speedup vs baseline: 1.5648x; 1.5648x over previous
#include <cuda_runtime.h>
#include <cuda_bf16.h>
#include <math_constants.h>

// Problem constants (fixed shapes)
#define BB 64
#define LL 512
#define HH 768
#define TT 9
#define NROWS (BB * LL)

__device__ float g_llh[BB];
__device__ float g_logits_scratch[BB * LL * TT];   // fallback if out has no room

// ---------------------------------------------------------------------------
// Kernel A: logits = hidden @ W + b   — one THREAD per output row.
// hidden: float4 loads, unroll 4 (high MLP, coalesced-by-reuse via sectors).
// W in smem, padded rows of 12 floats; loads are warp-uniform -> broadcast.
// Regs ~48 -> high occupancy. 128 blocks x 256 threads = 32768 rows exactly.
// ---------------------------------------------------------------------------
__global__ __launch_bounds__(256) void logits_kernel(
    const float* __restrict__ hidden,
    const float* __restrict__ W,
    const float* __restrict__ bias,
    float* __restrict__ logits)
{
    __shared__ float Ws[HH * 12];   // 36864 B
    __shared__ float bs[TT];

    for (int i = threadIdx.x; i < HH * TT; i += 256) {
        int k = i / 9;
        int t = i - 9 * k;
        Ws[12 * k + t] = W[i];
    }
    if (threadIdx.x < TT) bs[threadIdx.x] = bias[threadIdx.x];
    __syncthreads();

    const int row = blockIdx.x * 256 + threadIdx.x;
    const float4* h = (const float4*)(hidden + (size_t)row * HH);

    float acc[TT];
    #pragma unroll
    for (int t = 0; t < TT; t++) acc[t] = bs[t];

    #pragma unroll 2
    for (int kb = 0; kb < HH / 4; kb += 4) {
        float4 hv[4];
        #pragma unroll
        for (int u = 0; u < 4; u++) hv[u] = h[kb + u];

        #pragma unroll
        for (int u = 0; u < 4; u++) {
            float hx[4] = {hv[u].x, hv[u].y, hv[u].z, hv[u].w};
            #pragma unroll
            for (int kk = 0; kk < 4; kk++) {
                const int k = (kb + u) * 4 + kk;
                const float4 wa = *(const float4*)&Ws[12 * k];
                const float4 wb = *(const float4*)&Ws[12 * k + 4];
                const float  wc = Ws[12 * k + 8];
                const float  hvv = hx[kk];
                acc[0] = fmaf(hvv, wa.x, acc[0]);
                acc[1] = fmaf(hvv, wa.y, acc[1]);
                acc[2] = fmaf(hvv, wa.z, acc[2]);
                acc[3] = fmaf(hvv, wa.w, acc[3]);
                acc[4] = fmaf(hvv, wb.x, acc[4]);
                acc[5] = fmaf(hvv, wb.y, acc[5]);
                acc[6] = fmaf(hvv, wb.z, acc[6]);
                acc[7] = fmaf(hvv, wb.w, acc[7]);
                acc[8] = fmaf(hvv, wc,   acc[8]);
            }
        }
    }

    float* o = logits + (size_t)row * TT;
    #pragma unroll
    for (int t = 0; t < TT; t++) o[t] = acc[t];
}

// ---------------------------------------------------------------------------
// Kernel B: per-batch CRF, block = 128 threads (4 warps).
// Phase 1 (all threads): load logits/mask/labels to smem, precompute
//   ee[t][j] = exp(e[t][j]) for the whole sequence (no transcendentals left
//   in the scan loop).
// Phase 2: warp 0 = linear-domain scan (9x9 matvec per step via shfl+fma,
//   power-of-two rescale every 8 steps); warp 1 = numerator.
// ---------------------------------------------------------------------------
__global__ __launch_bounds__(128) void crf_kernel(
    const float* __restrict__ logits,
    const int*   __restrict__ mask,
    const int*   __restrict__ labels,
    const float* __restrict__ start_trans,
    const float* __restrict__ end_trans,
    const float* __restrict__ trans)
{
    __shared__ float e_s[LL * TT];    // 18432 B (log-domain, for numerator)
    __shared__ float ee_s[LL * TT];   // 18432 B (exp'd, for scan)
    __shared__ float m_s[LL];
    __shared__ int   lab_s[LL];
    __shared__ float tr_s[TT * TT];
    __shared__ float st_s[TT];
    __shared__ float en_s[TT];
    __shared__ float num_sh;

    const int b    = blockIdx.x;
    const int tid  = threadIdx.x;
    const int lane = tid & 31;
    const int warp = tid >> 5;

    const float L2E = 1.4426950408889634f;
    const float LN2 = 0.6931471805599453f;

    const float* lg = logits + (size_t)b * LL * TT;
    #pragma unroll 4
    for (int i = tid; i < LL * TT; i += 128) {
        float e = lg[i];
        e_s[i]  = e;
        ee_s[i] = exp2f(e * L2E);
    }
    for (int i = tid; i < LL; i += 128) {
        int l = labels[(size_t)b * LL + i];
        lab_s[i] = (l == -100) ? 0 : l;
        m_s[i]   = (float)mask[(size_t)b * LL + i];
    }
    if (tid < TT * TT) tr_s[tid] = trans[tid];
    if (tid < TT) { st_s[tid] = start_trans[tid]; en_s[tid] = end_trans[tid]; }
    __syncthreads();

    // ---- numerator (warp 1) ----
    if (warp == 1) {
        float acc = 0.f;
        int   msum = 0;
        for (int t = lane; t < LL; t += 32) {
            msum += (m_s[t] != 0.f) ? 1 : 0;
            if (t >= 1) {
                int lp = lab_s[t - 1], lt = lab_s[t];
                acc = fmaf(tr_s[lp * TT + lt] + e_s[t * TT + lt], m_s[t], acc);
            }
        }
        #pragma unroll
        for (int off = 16; off > 0; off >>= 1) {
            acc  += __shfl_xor_sync(0xffffffffu, acc, off);
            msum += __shfl_xor_sync(0xffffffffu, msum, off);
        }
        if (lane == 0) {
            int seq_end = msum - 1;
            if (seq_end < 0) seq_end = 0;
            int l0 = lab_s[0];
            int llast = lab_s[seq_end];
            num_sh = st_s[l0] + e_s[l0] + acc + en_s[llast];
        }
    }

    // ---- denominator scan (warp 0), linear domain, no MUFU in loop ----
    float denom = 0.f;
    if (warp == 0) {
        const int j = (lane < TT) ? lane : (TT - 1);

        float et0 = exp2f(tr_s[0 * TT + j] * L2E);
        float et1 = exp2f(tr_s[1 * TT + j] * L2E);
        float et2 = exp2f(tr_s[2 * TT + j] * L2E);
        float et3 = exp2f(tr_s[3 * TT + j] * L2E);
        float et4 = exp2f(tr_s[4 * TT + j] * L2E);
        float et5 = exp2f(tr_s[5 * TT + j] * L2E);
        float et6 = exp2f(tr_s[6 * TT + j] * L2E);
        float et7 = exp2f(tr_s[7 * TT + j] * L2E);
        float et8 = exp2f(tr_s[8 * TT + j] * L2E);

        float q = exp2f((st_s[j] + e_s[j]) * L2E);
        int   E = 0;

        float eej_next = ee_s[1 * TT + j];
        float ms_next  = m_s[1];

        for (int t = 1; t < LL; t++) {
            const float eej = eej_next;
            const float ms  = ms_next;
            if (t < LL - 1) {
                eej_next = ee_s[(t + 1) * TT + j];
                ms_next  = m_s[t + 1];
            }

            float p0 = __shfl_sync(0xffffffffu, q, 0);
            float p1 = __shfl_sync(0xffffffffu, q, 1);
            float p2 = __shfl_sync(0xffffffffu, q, 2);
            float p3 = __shfl_sync(0xffffffffu, q, 3);
            float p4 = __shfl_sync(0xffffffffu, q, 4);
            float p5 = __shfl_sync(0xffffffffu, q, 5);
            float p6 = __shfl_sync(0xffffffffu, q, 6);
            float p7 = __shfl_sync(0xffffffffu, q, 7);
            float p8 = __shfl_sync(0xffffffffu, q, 8);

            float a  = fmaf(p1, et1, p0 * et0);  a  = fmaf(p2, et2, a);
            float b2 = fmaf(p4, et4, p3 * et3);  b2 = fmaf(p5, et5, b2);
            float c  = fmaf(p7, et7, p6 * et6);  c  = fmaf(p8, et8, c);
            float s  = ((a + b2) + c) * eej;

            q = (ms != 0.f) ? s : q;

            if ((t & 7) == 7) {
                float q0 = __shfl_sync(0xffffffffu, q, 0);
                int ex = (__float_as_int(q0) >> 23) & 0xFF;
                float sc = __int_as_float((254 - ex) << 23);  // 2^(127-ex)
                q *= sc;
                E += ex - 127;
            }
        }

        // denom = ln( sum_j q[j]*exp(end[j]) ) + E*ln2
        float v = (lane < TT) ? q * exp2f(en_s[j] * L2E) : 0.f;
        #pragma unroll
        for (int off = 16; off > 0; off >>= 1)
            v += __shfl_xor_sync(0xffffffffu, v, off);
        denom = LN2 * (__log2f(v) + (float)E);
    }

    __syncthreads();   // num_sh ready
    if (warp == 0 && lane == 0)
        g_llh[b] = num_sh - denom;
}

// ---------------------------------------------------------------------------
// Kernel C: loss = -mean(llh), deterministic tree reduce
// ---------------------------------------------------------------------------
__global__ void loss_kernel(float* __restrict__ loss_out)
{
    int lane = threadIdx.x;   // 32 threads
    float v = g_llh[lane] + g_llh[lane + 32];
    #pragma unroll
    for (int off = 16; off > 0; off >>= 1)
        v += __shfl_xor_sync(0xffffffffu, v, off);
    if (lane == 0) loss_out[0] = -v * (1.0f / (float)BB);
}

// ---------------------------------------------------------------------------
extern "C" void kernel_launch(void* const* d_in, const int* in_sizes, int n_in,
                              void* d_out, int out_size)
{
    const float* hidden      = (const float*)d_in[0];
    const int*   attn_mask   = (const int*)d_in[1];
    const int*   labels      = (const int*)d_in[2];   // int32 (JAX x64 disabled)
    const float* W           = (const float*)d_in[3];
    const float* bias        = (const float*)d_in[4];
    const float* start_trans = (const float*)d_in[5];
    const float* end_trans   = (const float*)d_in[6];
    const float* trans       = (const float*)d_in[7];

    float* out = (float*)d_out;

    static float* scratch = nullptr;
    if (!scratch) {
        void* p = nullptr;
        cudaGetSymbolAddress(&p, g_logits_scratch);
        scratch = (float*)p;
    }

    const int NLOG = BB * LL * TT;   // 294912
    float* loss_ptr;
    float* logits_ptr;
    if (out_size >= NLOG + 1) {          // (loss, logits) concatenated
        loss_ptr   = out;
        logits_ptr = out + 1;
    } else if (out_size == NLOG) {       // logits only
        loss_ptr   = scratch;
        logits_ptr = out;
    } else {                             // loss only
        loss_ptr   = out;
        logits_ptr = scratch;
    }

    logits_kernel<<<128, 256>>>(hidden, W, bias, logits_ptr);
    crf_kernel<<<BB, 128>>>(logits_ptr, attn_mask, labels,
                            start_trans, end_trans, trans);
    loss_kernel<<<1, 32>>>(loss_ptr);
}